// round 9
// baseline (speedup 1.0000x reference)
#include <cuda_runtime.h>
#include <cstdint>

// ---------------- problem constants ----------------
#define B_   4
#define S_   12
#define N_   512
#define CIN  3
#define COUT 3
#define HID_ 64
#define HEADS_ 8
#define DH_  8
#define L_   2
#define E_   8192
#define BSN  (B_*S_*N_)          // 24576
#define BS_  (B_*S_)             // 48
#define SCALE_ 0.35355339059327373f

typedef unsigned long long u64;

// ---------------- f32x2 packed helpers (sm_100+) ----------------
__device__ __forceinline__ u64 pk2(float lo, float hi) {
    u64 r; asm("mov.b64 %0, {%1,%2};" : "=l"(r) : "f"(lo), "f"(hi)); return r;
}
__device__ __forceinline__ void upk2(u64 v, float& lo, float& hi) {
    asm("mov.b64 {%0,%1}, %2;" : "=f"(lo), "=f"(hi) : "l"(v));
}
__device__ __forceinline__ u64 fma2(u64 a, u64 b, u64 c) {
    u64 d; asm("fma.rn.f32x2 %0, %1, %2, %3;" : "=l"(d) : "l"(a), "l"(b), "l"(c)); return d;
}
__device__ __forceinline__ u64 mul2(u64 a, u64 b) {
    u64 d; asm("mul.rn.f32x2 %0, %1, %2;" : "=l"(d) : "l"(a), "l"(b)); return d;
}

// ---------------- device scratch ----------------
__device__ float g_h[BSN * HID_];
__device__ float g_q[BSN * HID_];
__device__ float g_k[BSN * HID_];
__device__ float g_v[BSN * HID_];
__device__ u64   g_mbits[N_ * 8];      // bitmask: row n, 512 key-bits

// ---------------- mask build: single block, smem staged ----------------
__global__ __launch_bounds__(1024) void mask_build_kernel(const int* __restrict__ ei) {
    __shared__ unsigned int mb[N_ * 16];   // 32KB bitmask
    int tid = threadIdx.x;
#pragma unroll
    for (int i = 0; i < 8; i++) mb[tid + i * 1024] = 0u;
    __syncthreads();
#pragma unroll
    for (int i = 0; i < 8; i++) {
        int e = tid + i * 1024;
        int src = ei[e];
        int dst = ei[E_ + e];
        atomicOr(&mb[src * 16 + (dst >> 5)], 1u << (dst & 31));
    }
    __syncthreads();
    unsigned int* gm = (unsigned int*)g_mbits;
#pragma unroll
    for (int i = 0; i < 8; i++) gm[tid + i * 1024] = mb[tid + i * 1024];
}

// ---------------- input projection ----------------
__global__ void in_proj_kernel(const float* __restrict__ x,
                               const float* __restrict__ Win,
                               const float* __restrict__ b_in) {
    int idx = blockIdx.x * blockDim.x + threadIdx.x;
    int j = idx & 63;
    int r = idx >> 6;
    const float* xr = x + r * 3;
    const float* w  = Win + j * 3;
    float s = b_in[j];
    s += xr[0] * w[0];
    s += xr[1] * w[1];
    s += xr[2] * w[2];
    g_h[idx] = s;
}

// ---------------- QKV projection: fused q/k/v, occupancy-optimized ----------
// 256 threads, 64 rows x 64 cols, thread tile 4r x 4c (acc = 8 u64).
// hT[d][r], wT[d][j] with XOR swizzle (r ^ ((d&15)<<2)): h reads broadcast
// conflict-free, w reads <=2-way. 36.9KB smem -> ~6 blocks/SM.
#define ST 72

__global__ __launch_bounds__(256) void qkv_proj_kernel(
    const float* __restrict__ Wq, const float* __restrict__ bq,
    const float* __restrict__ Wk, const float* __restrict__ bk,
    const float* __restrict__ Wv, const float* __restrict__ bv) {
    __shared__ float hT[64 * ST];
    __shared__ float wT[64 * ST];

    int tid = threadIdx.x;
    int r0 = blockIdx.x * 64;

    const float* Ws[3] = {Wq, Wk, Wv};
    const float* bs[3] = {bq, bk, bv};
    float* outs[3] = {g_q, g_k, g_v};

    // stage hT once (transposed + swizzled); coalesced global reads
#pragma unroll
    for (int i = 0; i < 16; i++) {
        int idx = tid + i * 256;
        int d = idx & 63, r = idx >> 6;
        hT[d * ST + (r ^ ((d & 15) << 2))] = g_h[(size_t)(r0 + r) * 64 + d];
    }

    int cg = tid & 15;    // cols cg*4..+3
    int rg = tid >> 4;    // rows rg*4..+3
    int rb = rg << 2;
    int cb = cg << 2;

#pragma unroll 1
    for (int m = 0; m < 3; m++) {
        const float* W = Ws[m];
        if (m) __syncthreads();   // previous wT readers done
#pragma unroll
        for (int i = 0; i < 16; i++) {
            int idx = tid + i * 256;
            int d = idx & 63, j = idx >> 6;
            wT[d * ST + (j ^ ((d & 15) << 2))] = W[idx];
        }
        __syncthreads();

        u64 acc[4][2];
#pragma unroll
        for (int a = 0; a < 4; a++) { acc[a][0] = 0ull; acc[a][1] = 0ull; }

#pragma unroll 8
        for (int d = 0; d < 64; d++) {
            int s = (d & 15) << 2;
            float4 hv = *(const float4*)(hT + d * ST + (rb ^ s));
            float4 wv = *(const float4*)(wT + d * ST + (cb ^ s));
            u64 w0 = pk2(wv.x, wv.y);
            u64 w1 = pk2(wv.z, wv.w);
            u64 h0 = pk2(hv.x, hv.x);
            u64 h1 = pk2(hv.y, hv.y);
            u64 h2 = pk2(hv.z, hv.z);
            u64 h3 = pk2(hv.w, hv.w);
            acc[0][0] = fma2(h0, w0, acc[0][0]);
            acc[0][1] = fma2(h0, w1, acc[0][1]);
            acc[1][0] = fma2(h1, w0, acc[1][0]);
            acc[1][1] = fma2(h1, w1, acc[1][1]);
            acc[2][0] = fma2(h2, w0, acc[2][0]);
            acc[2][1] = fma2(h2, w1, acc[2][1]);
            acc[3][0] = fma2(h3, w0, acc[3][0]);
            acc[3][1] = fma2(h3, w1, acc[3][1]);
        }

        float4 b4 = *(const float4*)(bs[m] + cb);
        float* out = outs[m];
#pragma unroll
        for (int i = 0; i < 4; i++) {
            float lo0, hi0, lo1, hi1;
            upk2(acc[i][0], lo0, hi0);
            upk2(acc[i][1], lo1, hi1);
            float4 o;
            o.x = lo0 + b4.x; o.y = hi0 + b4.y;
            o.z = lo1 + b4.z; o.w = hi1 + b4.w;
            *(float4*)(out + (size_t)(r0 + rb + i) * 64 + cb) = o;
        }
    }
}

// ---------------- sparse spatial attention: warp per query ----------------
__global__ __launch_bounds__(256) void spatial_attn_kernel() {
    int lane = threadIdx.x & 31;
    int warp = threadIdx.x >> 5;
    int bs = blockIdx.y;
    int nq = blockIdx.x * 8 + warp;
    int d0 = lane * 2;

    const float* qb = g_q + ((size_t)bs * N_ + nq) * 64;
    u64 q2 = mul2(*(const u64*)(qb + d0), pk2(SCALE_, SCALE_));

    const float* kb = g_k + (size_t)bs * N_ * 64;
    const float* vb = g_v + (size_t)bs * N_ * 64;
    const u64* mrow = g_mbits + (size_t)nq * 8;

    float m_run = -1e30f, l_run = 0.f;
    u64 acc = 0ull;

#pragma unroll 1
    for (int c = 0; c < 8; c++) {
        u64 bits = mrow[c];            // uniform across warp
        int base = c * 64;
        while (bits) {
            int i = __ffsll((long long)bits) - 1;
            bits &= bits - 1;
            int m = base + i;
            u64 k2 = *(const u64*)(kb + (size_t)m * 64 + d0);
            u64 v2 = *(const u64*)(vb + (size_t)m * 64 + d0);
            float lo, hi;
            upk2(mul2(q2, k2), lo, hi);
            float pd = lo + hi;
            pd += __shfl_xor_sync(0xFFFFFFFFu, pd, 1);
            pd += __shfl_xor_sync(0xFFFFFFFFu, pd, 2);
            float mn = fmaxf(m_run, pd);
            float corr = __expf(m_run - mn);
            float p = __expf(pd - mn);
            l_run = fmaf(l_run, corr, p);
            acc = fma2(pk2(p, p), v2, mul2(acc, pk2(corr, corr)));
            m_run = mn;
        }
    }

    float o0, o1;
    if (l_run > 0.f) {
        upk2(acc, o0, o1);
        float inv = 1.f / l_run;
        o0 *= inv; o1 *= inv;
    } else {
        // no unmasked keys: softmax of all -1e9 -> uniform over 512
        o0 = o1 = 0.f;
        for (int m = 0; m < N_; m++) {
            float2 v = *(const float2*)(vb + (size_t)m * 64 + d0);
            o0 += v.x; o1 += v.y;
        }
        o0 *= (1.f / N_); o1 *= (1.f / N_);
    }
    *(u64*)(g_h + ((size_t)bs * N_ + nq) * 64 + d0) = pk2(o0, o1);
}

// ---------------- temporal attention (S=12) + fused final out-proj ----------
__global__ __launch_bounds__(128) void temporal_attn_kernel(
    const float* __restrict__ Wout, const float* __restrict__ bout,
    float* __restrict__ out, int last) {
    __shared__ float ksh[12 * 64];
    __shared__ float vsh[12 * 64];
    __shared__ float osh[64];
    int tid = threadIdx.x;
    int b = blockIdx.x >> 9;
    int n = blockIdx.x & 511;
    for (int i = tid; i < 12 * 64; i += 128) {
        int t = i >> 6, c = i & 63;
        size_t g = (((size_t)b * 12 + t) * N_ + n) * 64 + c;
        ksh[i] = g_k[g];
        vsh[i] = g_v[g];
    }
    __syncthreads();
    if (tid < 96) {
        int s = tid >> 3, hh = tid & 7;
        const float* qr = g_q + (((size_t)b * 12 + s) * N_ + n) * 64 + hh * 8;
        float qv[8];
#pragma unroll
        for (int d = 0; d < 8; d++) qv[d] = qr[d];
        float sc[12];
        float mx = -1e30f;
#pragma unroll
        for (int t = 0; t < 12; t++) {
            float dot = 0.f;
#pragma unroll
            for (int d = 0; d < 8; d++) dot = fmaf(qv[d], ksh[t * 64 + hh * 8 + d], dot);
            sc[t] = dot * SCALE_;
            mx = fmaxf(mx, sc[t]);
        }
        float l = 0.f;
#pragma unroll
        for (int t = 0; t < 12; t++) {
            sc[t] = __expf(sc[t] - mx);
            l += sc[t];
        }
        float acc[8];
#pragma unroll
        for (int d = 0; d < 8; d++) acc[d] = 0.f;
#pragma unroll
        for (int t = 0; t < 12; t++) {
#pragma unroll
            for (int d = 0; d < 8; d++)
                acc[d] = fmaf(sc[t], vsh[t * 64 + hh * 8 + d], acc[d]);
        }
        float inv = 1.f / l;
        float* orow = g_h + (((size_t)b * 12 + s) * N_ + n) * 64 + hh * 8;
#pragma unroll
        for (int d = 0; d < 8; d++) {
            float o = acc[d] * inv;
            orow[d] = o;
            if (last && s == 11) osh[hh * 8 + d] = o;
        }
    }
    if (last) {
        __syncthreads();
        if (tid < 3) {
            float s = bout[tid];
            const float* w = Wout + tid * 64;
#pragma unroll 16
            for (int d = 0; d < 64; d++) s = fmaf(osh[d], w[d], s);
            out[((size_t)b * N_ + n) * 3 + tid] = s;
        }
    }
}

// ---------------- launch ----------------
extern "C" void kernel_launch(void* const* d_in, const int* in_sizes, int n_in,
                              void* d_out, int out_size) {
    const float* x    = (const float*)d_in[0];
    const int*   ei   = (const int*)d_in[1];
    const float* Win  = (const float*)d_in[2];
    const float* b_in = (const float*)d_in[3];
    const float* Wqs  = (const float*)d_in[4];
    const float* bqs  = (const float*)d_in[5];
    const float* Wks  = (const float*)d_in[6];
    const float* bks  = (const float*)d_in[7];
    const float* Wvs  = (const float*)d_in[8];
    const float* bvs  = (const float*)d_in[9];
    const float* Wqt  = (const float*)d_in[10];
    const float* bqt  = (const float*)d_in[11];
    const float* Wkt  = (const float*)d_in[12];
    const float* bkt  = (const float*)d_in[13];
    const float* Wvt  = (const float*)d_in[14];
    const float* bvt  = (const float*)d_in[15];
    const float* Wout = (const float*)d_in[16];
    const float* bout = (const float*)d_in[17];
    float* out = (float*)d_out;

    mask_build_kernel<<<1, 1024>>>(ei);
    in_proj_kernel<<<(BSN * HID_) / 256, 256>>>(x, Win, b_in);

    for (int l = 0; l < L_; l++) {
        qkv_proj_kernel<<<BSN / 64, 256>>>(
            Wqs + l * 4096, bqs + l * 64,
            Wks + l * 4096, bks + l * 64,
            Wvs + l * 4096, bvs + l * 64);
        spatial_attn_kernel<<<dim3(64, BS_), 256>>>();
        qkv_proj_kernel<<<BSN / 64, 256>>>(
            Wqt + l * 4096, bqt + l * 64,
            Wkt + l * 4096, bkt + l * 64,
            Wvt + l * 4096, bvt + l * 64);
        temporal_attn_kernel<<<B_ * N_, 128>>>(Wout, bout, out, l == L_ - 1);
    }
}